// round 1
// baseline (speedup 1.0000x reference)
#include <cuda_runtime.h>

// Problem constants
#define BATCH 64
#define D 256
#define NTOK 4095

// Internal node values: nodes 0..2046, layout [node][batch][d]
__device__ float g_node_val[2047 * BATCH * D];
// Transposed weights, layout [k][j]: k 0..767 = W_in, 768..1023 = W1, 1024..1279 = W2
__device__ float g_Wt[1280 * D];

__global__ void transpose_weights(const float* __restrict__ W_in,
                                  const float* __restrict__ W1,
                                  const float* __restrict__ W2) {
    int idx = blockIdx.x * blockDim.x + threadIdx.x;
    if (idx >= 1280 * D) return;
    int k = idx / D, j = idx % D;
    float v;
    if (k < 768)        v = W_in[j * 768 + k];
    else if (k < 1024)  v = W1[j * 256 + (k - 768)];
    else                v = W2[j * 256 + (k - 1024)];
    g_Wt[idx] = v;
}

// Block = one tree node, M = 64 batch rows, N = 256 (full), fused 3-layer MLP.
// SMEM: hbuf[64][256] activation staging, Ws[32][256] weight k-chunk, As[64][40] input chunk, toks[3][64]
__global__ void __launch_bounds__(256, 2)
level_kernel(const int* __restrict__ tokens, const float* __restrict__ E,
             const float* __restrict__ b_in, const float* __restrict__ b1,
             const float* __restrict__ b2, float* __restrict__ d_out, int level)
{
    extern __shared__ float sm[];
    float* hbuf = sm;                    // 16384 floats
    float* Ws   = sm + 16384;            // 8192 floats
    float* As   = sm + 16384 + 8192;     // 64*40 = 2560 floats (padded stride 40)
    int*   toks = (int*)(sm + 16384 + 8192 + 2560); // 3*64 ints

    const int t  = threadIdx.x;
    const int tn = t & 31;
    const int tm = t >> 5;
    const int node = level - 1 + blockIdx.x;
    const bool leaf = (level == 1024);

    // Load token indices: roots always; children only at leaf level.
    if (t < BATCH) {
        toks[t] = tokens[t * NTOK + node];
    } else if (leaf && t < 2 * BATCH) {
        int b = t - BATCH;
        toks[t] = tokens[b * NTOK + (2 * node + 1)];
    } else if (leaf && t < 3 * BATCH) {
        int b = t - 2 * BATCH;
        toks[t] = tokens[b * NTOK + (2 * node + 2)];
    }
    // (first __syncthreads inside chunk loop covers this)

    float acc[8][8];

    // ================= Layer 1: K = 768 =================
    #pragma unroll
    for (int i = 0; i < 8; ++i)
        #pragma unroll
        for (int j = 0; j < 8; ++j) acc[i][j] = 0.f;

    for (int c = 0; c < 24; ++c) {
        __syncthreads();
        // Load W chunk (8192 floats, contiguous)
        {
            const float4* src = (const float4*)(g_Wt + c * 32 * D);
            float4* dst = (float4*)Ws;
            #pragma unroll
            for (int r = 0; r < 8; ++r) dst[t + r * 256] = src[t + r * 256];
        }
        // Load A chunk: 64 rows x 32 k
        {
            int b = t >> 2;
            int q = t & 3;
            const float* src;
            if (c < 8) {
                src = E + (size_t)toks[b] * D + c * 32;
            } else if (c < 16) {
                if (leaf) src = E + (size_t)toks[BATCH + b] * D + (c - 8) * 32;
                else      src = g_node_val + ((size_t)(2 * node + 1) * BATCH + b) * D + (c - 8) * 32;
            } else {
                if (leaf) src = E + (size_t)toks[2 * BATCH + b] * D + (c - 16) * 32;
                else      src = g_node_val + ((size_t)(2 * node + 2) * BATCH + b) * D + (c - 16) * 32;
            }
            float4 v0 = *(const float4*)(src + q * 4);
            float4 v1 = *(const float4*)(src + (q + 4) * 4);
            *(float4*)(As + b * 40 + q * 4)       = v0;
            *(float4*)(As + b * 40 + (q + 4) * 4) = v1;
        }
        __syncthreads();
        // Compute
        const float* Ap = As + tm * 8 * 40;
        #pragma unroll
        for (int kk = 0; kk < 32; ++kk) {
            float4 w0 = *(const float4*)(Ws + kk * 256 + tn * 4);
            float4 w1 = *(const float4*)(Ws + kk * 256 + tn * 4 + 128);
            #pragma unroll
            for (int i = 0; i < 8; ++i) {
                float a = Ap[i * 40 + kk];
                acc[i][0] += a * w0.x; acc[i][1] += a * w0.y;
                acc[i][2] += a * w0.z; acc[i][3] += a * w0.w;
                acc[i][4] += a * w1.x; acc[i][5] += a * w1.y;
                acc[i][6] += a * w1.z; acc[i][7] += a * w1.w;
            }
        }
    }

    // bias + ELU -> hbuf
    {
        float4 bb0 = *(const float4*)(b_in + tn * 4);
        float4 bb1 = *(const float4*)(b_in + tn * 4 + 128);
        float bv[8] = {bb0.x, bb0.y, bb0.z, bb0.w, bb1.x, bb1.y, bb1.z, bb1.w};
        #pragma unroll
        for (int i = 0; i < 8; ++i) {
            int row = tm * 8 + i;
            #pragma unroll
            for (int j = 0; j < 8; ++j) {
                int col = tn * 4 + (j & 3) + (j >> 2) * 128;
                float v = acc[i][j] + bv[j];
                v = v > 0.f ? v : (expf(v) - 1.f);
                hbuf[row * 256 + col] = v;
            }
        }
    }

    // ================= Layer 2: K = 256 =================
    #pragma unroll
    for (int i = 0; i < 8; ++i)
        #pragma unroll
        for (int j = 0; j < 8; ++j) acc[i][j] = 0.f;

    for (int c = 0; c < 8; ++c) {
        __syncthreads();  // (c==0: guards hbuf writes + prior Ws reads)
        {
            const float4* src = (const float4*)(g_Wt + (768 + c * 32) * D);
            float4* dst = (float4*)Ws;
            #pragma unroll
            for (int r = 0; r < 8; ++r) dst[t + r * 256] = src[t + r * 256];
        }
        __syncthreads();
        const float* Ap = hbuf + tm * 8 * 256 + c * 32;
        #pragma unroll
        for (int kk = 0; kk < 32; ++kk) {
            float4 w0 = *(const float4*)(Ws + kk * 256 + tn * 4);
            float4 w1 = *(const float4*)(Ws + kk * 256 + tn * 4 + 128);
            #pragma unroll
            for (int i = 0; i < 8; ++i) {
                float a = Ap[i * 256 + kk];
                acc[i][0] += a * w0.x; acc[i][1] += a * w0.y;
                acc[i][2] += a * w0.z; acc[i][3] += a * w0.w;
                acc[i][4] += a * w1.x; acc[i][5] += a * w1.y;
                acc[i][6] += a * w1.z; acc[i][7] += a * w1.w;
            }
        }
    }

    __syncthreads();  // all hbuf reads done before overwrite
    {
        float4 bb0 = *(const float4*)(b1 + tn * 4);
        float4 bb1 = *(const float4*)(b1 + tn * 4 + 128);
        float bv[8] = {bb0.x, bb0.y, bb0.z, bb0.w, bb1.x, bb1.y, bb1.z, bb1.w};
        #pragma unroll
        for (int i = 0; i < 8; ++i) {
            int row = tm * 8 + i;
            #pragma unroll
            for (int j = 0; j < 8; ++j) {
                int col = tn * 4 + (j & 3) + (j >> 2) * 128;
                float v = acc[i][j] + bv[j];
                v = v > 0.f ? v : (expf(v) - 1.f);
                hbuf[row * 256 + col] = v;
            }
        }
    }

    // ================= Layer 3: K = 256 =================
    #pragma unroll
    for (int i = 0; i < 8; ++i)
        #pragma unroll
        for (int j = 0; j < 8; ++j) acc[i][j] = 0.f;

    for (int c = 0; c < 8; ++c) {
        __syncthreads();
        {
            const float4* src = (const float4*)(g_Wt + (1024 + c * 32) * D);
            float4* dst = (float4*)Ws;
            #pragma unroll
            for (int r = 0; r < 8; ++r) dst[t + r * 256] = src[t + r * 256];
        }
        __syncthreads();
        const float* Ap = hbuf + tm * 8 * 256 + c * 32;
        #pragma unroll
        for (int kk = 0; kk < 32; ++kk) {
            float4 w0 = *(const float4*)(Ws + kk * 256 + tn * 4);
            float4 w1 = *(const float4*)(Ws + kk * 256 + tn * 4 + 128);
            #pragma unroll
            for (int i = 0; i < 8; ++i) {
                float a = Ap[i * 256 + kk];
                acc[i][0] += a * w0.x; acc[i][1] += a * w0.y;
                acc[i][2] += a * w0.z; acc[i][3] += a * w0.w;
                acc[i][4] += a * w1.x; acc[i][5] += a * w1.y;
                acc[i][6] += a * w1.z; acc[i][7] += a * w1.w;
            }
        }
    }

    // Epilogue: + b2 + residual root embedding, write out
    {
        float4 bb0 = *(const float4*)(b2 + tn * 4);
        float4 bb1 = *(const float4*)(b2 + tn * 4 + 128);
        float bv[8] = {bb0.x, bb0.y, bb0.z, bb0.w, bb1.x, bb1.y, bb1.z, bb1.w};
        #pragma unroll
        for (int i = 0; i < 8; ++i) {
            int row = tm * 8 + i;
            const float* Er = E + (size_t)toks[row] * D;
            float4 r0 = *(const float4*)(Er + tn * 4);
            float4 r1 = *(const float4*)(Er + tn * 4 + 128);
            float rv[8] = {r0.x, r0.y, r0.z, r0.w, r1.x, r1.y, r1.z, r1.w};
            #pragma unroll
            for (int j = 0; j < 8; ++j) {
                int col = tn * 4 + (j & 3) + (j >> 2) * 128;
                float v = acc[i][j] + bv[j] + rv[j];
                if (level == 1) {
                    d_out[row * D + col] = v;
                } else {
                    g_node_val[((size_t)node * BATCH + row) * D + col] = v;
                }
            }
        }
    }
}

extern "C" void kernel_launch(void* const* d_in, const int* in_sizes, int n_in,
                              void* d_out, int out_size) {
    const int*   tokens = (const int*)d_in[0];
    const float* E      = (const float*)d_in[1];
    const float* W_in   = (const float*)d_in[2];
    const float* b_in   = (const float*)d_in[3];
    const float* W1     = (const float*)d_in[4];
    const float* b1     = (const float*)d_in[5];
    const float* W2     = (const float*)d_in[6];
    const float* b2     = (const float*)d_in[7];
    float* out = (float*)d_out;

    transpose_weights<<<(1280 * D + 255) / 256, 256>>>(W_in, W1, W2);

    const int SMEM = (16384 + 8192 + 2560) * 4 + 3 * 64 * 4;  // 109312 B
    cudaFuncSetAttribute(level_kernel, cudaFuncAttributeMaxDynamicSharedMemorySize, SMEM);

    for (int level = 1024; level >= 1; level >>= 1) {
        level_kernel<<<level, 256, SMEM>>>(tokens, E, b_in, b1, b2, out, level);
    }
}